// round 1
// baseline (speedup 1.0000x reference)
#include <cuda_runtime.h>

// Problem constants (fixed by the dataset): B=8,H=8,L=1024,DK=1024,DV=64; L==DK.
#define NB 8
#define NH 8
#define NL 1024
#define NDK 1024
#define NDV 64
#define NROWS (NB*NH*NL)        // 65536 rows of Q / K
#define NBH   (NB*NH)           // 64

// Scratch (allocation-free rule: __device__ globals)
__device__ float g_qrs[NROWS];  // rowsum over k of elu(Q)+1
__device__ float g_krs[NROWS];  // rowsum over k of elu(K)+1
__device__ float g_kcs[NROWS];  // colsum over l of elu(K)+1, laid out [bh][k]

__global__ void init_kcs_kernel() {
    int i = blockIdx.x * blockDim.x + threadIdx.x;
    g_kcs[i] = 0.0f;
}

__device__ __forceinline__ float elu1(float x) {
    // elu(x)+1 : x>0 -> x+1 ; x<=0 -> exp(x)
    return x > 0.0f ? x + 1.0f : __expf(x);
}

// One block = 32 consecutive rows (one (b,h) owns 32 such tiles).
// 256 threads; thread t owns float4 column chunk t (columns 4t..4t+3) for
// every row in the tile. Per row: warp-level shuffle reduce -> 8 partials in
// smem, reduced at the end by threads 0..31. Column partials accumulate in
// registers across the 32 rows and flush with 4 spread-address atomicAdds.
template <bool DO_COL>
__global__ __launch_bounds__(256) void reduce_kernel(const float4* __restrict__ X) {
    __shared__ float sm[32 * 8];
    const int t  = threadIdx.x;
    const int w  = t >> 5;
    const int ln = t & 31;
    const int bt = blockIdx.x;                    // tile index, 2048 tiles

    const float4* p = X + (size_t)bt * 32 * 256 + t;   // 256 float4 per row

    float c0 = 0.f, c1 = 0.f, c2 = 0.f, c3 = 0.f;

#pragma unroll 8
    for (int r = 0; r < 32; r++) {
        float4 v = p[(size_t)r * 256];
        float e0 = elu1(v.x), e1 = elu1(v.y), e2 = elu1(v.z), e3 = elu1(v.w);
        if (DO_COL) { c0 += e0; c1 += e1; c2 += e2; c3 += e3; }
        float s = (e0 + e1) + (e2 + e3);
        s += __shfl_xor_sync(0xffffffffu, s, 16);
        s += __shfl_xor_sync(0xffffffffu, s, 8);
        s += __shfl_xor_sync(0xffffffffu, s, 4);
        s += __shfl_xor_sync(0xffffffffu, s, 2);
        s += __shfl_xor_sync(0xffffffffu, s, 1);
        if (ln == 0) sm[r * 8 + w] = s;
    }
    __syncthreads();

    if (t < 32) {
        float s = 0.f;
#pragma unroll
        for (int i = 0; i < 8; i++) s += sm[t * 8 + i];
        if (DO_COL) g_krs[bt * 32 + t] = s;
        else        g_qrs[bt * 32 + t] = s;
    }

    if (DO_COL) {
        const int bh = bt >> 5;                   // 32 tiles per (b,h)
        float* base = g_kcs + bh * 1024 + t * 4;
        atomicAdd(base + 0, c0);
        atomicAdd(base + 1, c1);
        atomicAdd(base + 2, c2);
        atomicAdd(base + 3, c3);
    }
}

// out[row, v] = Qrs[row]*Krs[row] / (Qrs[row]*Kcs[row] + eps) * V[row, v]
// (Kcs indexed by l since k==l; layout [bh][l] == flat row index.)
__global__ __launch_bounds__(256) void finalize_kernel(const float4* __restrict__ V,
                                                       float4* __restrict__ O) {
    int i   = blockIdx.x * blockDim.x + threadIdx.x;  // 0 .. 1048575 (16 f4/row)
    int row = i >> 4;
    float q = g_qrs[row];
    float k = g_krs[row];
    float c = g_kcs[row];
    float scale = __fdividef(q * k, q * c + 1e-6f);
    float4 v = V[i];
    v.x *= scale; v.y *= scale; v.z *= scale; v.w *= scale;
    O[i] = v;
}

extern "C" void kernel_launch(void* const* d_in, const int* in_sizes, int n_in,
                              void* d_out, int out_size) {
    const float4* Q = (const float4*)d_in[0];
    const float4* K = (const float4*)d_in[1];
    const float4* V = (const float4*)d_in[2];
    float4* O = (float4*)d_out;

    init_kcs_kernel<<<NROWS / 1024, 1024>>>();
    reduce_kernel<true ><<<NROWS / 32, 256>>>(K);   // Krs + Kcs
    reduce_kernel<false><<<NROWS / 32, 256>>>(Q);   // Qrs
    finalize_kernel<<<(NROWS * (NDV / 4)) / 256, 256>>>(V, O);
}